// round 14
// baseline (speedup 1.0000x reference)
#include <cuda_runtime.h>
#include <cuda_bf16.h>
#include <cstdint>

#define B_   2
#define C_   256
#define N_   4096
#define R_   8
#define G_   4
#define CG_  64
#define DB   4        // DIRS*B_

// ---------------- scratch ---------------------------------------------------
__device__ float g_q[DB][R_][N_];
__device__ float g_k[DB][R_][N_];
__device__ float g_v[DB][C_][N_];
__device__ float g_S[DB][N_];
__device__ __nv_bfloat16 g_vb[DB][C_][N_];          // v' in bf16 (A operand)
__device__ __nv_bfloat16 g_E[DB][N_][N_];           // Et[m][n] = exp(q_n . k_m)

// ---------------- helpers ----------------------------------------------------
__device__ __forceinline__ uint32_t smem_u32(const void* p) {
    uint32_t a;
    asm("{ .reg .u64 t; cvta.to.shared.u64 t, %1; cvt.u32.u64 %0, t; }" : "=r"(a) : "l"(p));
    return a;
}
#define SWZ(o) ((o) ^ (((o) >> 3) & 0x70))
#define CPA(s, g) asm volatile("cp.async.cg.shared.global [%0], [%1], 16;" :: "r"(s), "l"(g) : "memory")
#define CPC()     asm volatile("cp.async.commit_group;" ::: "memory")
#define CPW(n)    asm volatile("cp.async.wait_group %0;" :: "n"(n) : "memory")

__device__ __forceinline__ void ldsm4(uint32_t* r, uint32_t addr) {
    asm volatile("ldmatrix.sync.aligned.m8n8.x4.shared.b16 {%0,%1,%2,%3}, [%4];"
                 : "=r"(r[0]), "=r"(r[1]), "=r"(r[2]), "=r"(r[3]) : "r"(addr));
}
__device__ __forceinline__ void mma16816(float* d, const uint32_t* a, uint32_t b0, uint32_t b1) {
    asm volatile("mma.sync.aligned.m16n8k16.row.col.f32.bf16.bf16.f32 "
                 "{%0,%1,%2,%3}, {%4,%5,%6,%7}, {%8,%9}, {%0,%1,%2,%3};"
                 : "+f"(d[0]), "+f"(d[1]), "+f"(d[2]), "+f"(d[3])
                 : "r"(a[0]), "r"(a[1]), "r"(a[2]), "r"(a[3]), "r"(b0), "r"(b1));
}

// ---------------- K1: fused low-rank projections (+ S zeroing folded in) -----
__global__ void k_qkproj(const float* __restrict__ fL, const float* __restrict__ fU,
                         const float* __restrict__ qLw, const float* __restrict__ qLb,
                         const float* __restrict__ kUw, const float* __restrict__ kUb,
                         const float* __restrict__ qUw, const float* __restrict__ qUb,
                         const float* __restrict__ kLw, const float* __restrict__ kLb) {
    __shared__ float sbuf[8448];
    int t = threadIdx.x;
    int n0 = blockIdx.x * 64;
    int b  = blockIdx.y;
    int nl = t & 63, slice = t >> 6;

    if (t < 64) {
        g_S[b][n0 + t] = 0.f;
        g_S[2 + b][n0 + t] = 0.f;
    }

    for (int i = t; i < R_ * C_; i += 256) {
        sbuf[i] = qLw[i]; sbuf[2048 + i] = kUw[i]; sbuf[4096 + i] = qUw[i]; sbuf[6144 + i] = kLw[i];
    }
    __syncthreads();

    float aQL[R_], aKU[R_], aQU[R_], aKL[R_];
#pragma unroll
    for (int r = 0; r < R_; r++) { aQL[r]=0.f; aKU[r]=0.f; aQU[r]=0.f; aKL[r]=0.f; }
    const float* xl = fL + (size_t)b * C_ * N_ + n0 + nl;
    const float* xu = fU + (size_t)b * C_ * N_ + n0 + nl;
    for (int ci = 0; ci < 64; ci++) {
        int c = slice * 64 + ci;
        float vl = xl[(size_t)c * N_];
        float vu = xu[(size_t)c * N_];
#pragma unroll
        for (int r = 0; r < R_; r++) {
            aQL[r] = fmaf(sbuf[r * 256 + c], vl, aQL[r]);
            aKU[r] = fmaf(sbuf[2048 + r * 256 + c], vu, aKU[r]);
            aQU[r] = fmaf(sbuf[4096 + r * 256 + c], vu, aQU[r]);
            aKL[r] = fmaf(sbuf[6144 + r * 256 + c], vl, aKL[r]);
        }
    }
    __syncthreads();
    {
        float* red = &sbuf[(size_t)(slice * 64 + nl) * 33];
#pragma unroll
        for (int r = 0; r < R_; r++) {
            red[r] = aQL[r]; red[8 + r] = aKU[r]; red[16 + r] = aQU[r]; red[24 + r] = aKL[r];
        }
    }
    __syncthreads();
    {
        int n2 = t & 63, grp = t >> 6;
#pragma unroll
        for (int j = 0; j < R_; j++) {
            int o = grp * 8 + j;
            float s = sbuf[(0 * 64 + n2) * 33 + o] + sbuf[(1 * 64 + n2) * 33 + o]
                    + sbuf[(2 * 64 + n2) * 33 + o] + sbuf[(3 * 64 + n2) * 33 + o];
            int n = n0 + n2;
            if (grp == 0)      g_q[b][j][n]     = s + qLb[j];
            else if (grp == 1) g_k[b][j][n]     = s + kUb[j];
            else if (grp == 2) g_q[2 + b][j][n] = s + qUb[j];
            else               g_k[2 + b][j][n] = s + kLb[j];
        }
    }
}

// ---------------- K2: grouped 1x1 convs -------------------------------------
__global__ void k_vconv(const float* __restrict__ fL, const float* __restrict__ fU,
                        const float* __restrict__ vUw, const float* __restrict__ vUb,
                        const float* __restrict__ vLw, const float* __restrict__ vLb) {
    __shared__ float xs[CG_][128];
    __shared__ float ws[CG_][CG_];
    int t  = threadIdx.x;
    int n0 = blockIdx.x * 128;
    int g  = blockIdx.y;
    int z  = blockIdx.z;
    int dir = z >> 1, b = z & 1;
    const float* x    = dir ? fL  : fU;
    const float* w    = dir ? vLw : vUw;
    const float* bias = dir ? vLb : vUb;
    for (int ci = 0; ci < CG_; ci++)
        xs[ci][t] = x[((size_t)b * C_ + g * CG_ + ci) * N_ + n0 + t];
    for (int i = t; i < CG_ * CG_; i += 128)
        (&ws[0][0])[i] = w[g * CG_ * CG_ + i];
    __syncthreads();
    for (int co = 0; co < CG_; co++) {
        float acc = bias[g * CG_ + co];
#pragma unroll 8
        for (int ci = 0; ci < CG_; ci++)
            acc = fmaf(ws[co][ci], xs[ci][t], acc);
        g_v[z][g * CG_ + co][n0 + t] = acc;
    }
}

// ---------------- K3: Et[m][n]=exp(q_n.k_m) bf16, coalesced, low-reg ---------
__global__ void __launch_bounds__(256) k_expT() {
    __shared__ float ks[64][9];
    __shared__ float sacc[8][128];
    int t = threadIdx.x, lane = t & 31, w = t >> 5;
    int m0 = blockIdx.x * 64;
    int n0 = blockIdx.y * 128;
    int z  = blockIdx.z;

    for (int i = t; i < 64 * R_; i += 256)
        ks[i >> 3][i & 7] = g_k[z][i & 7][m0 + (i >> 3)];

    float4 qr[R_];
#pragma unroll
    for (int r = 0; r < R_; r++)
        qr[r] = *(const float4*)&g_q[z][r][n0 + lane * 4];
    __syncthreads();

    float s0 = 0.f, s1 = 0.f, s2 = 0.f, s3 = 0.f;
#pragma unroll
    for (int mi = 0; mi < 8; mi++) {
        int mrow = w * 8 + mi;
        float l0 = 0.f, l1 = 0.f, l2 = 0.f, l3 = 0.f;
#pragma unroll
        for (int r = 0; r < R_; r++) {
            float km = ks[mrow][r];
            l0 = fmaf(qr[r].x, km, l0);
            l1 = fmaf(qr[r].y, km, l1);
            l2 = fmaf(qr[r].z, km, l2);
            l3 = fmaf(qr[r].w, km, l3);
        }
        float e0 = __expf(l0), e1 = __expf(l1), e2 = __expf(l2), e3 = __expf(l3);
        s0 += e0; s1 += e1; s2 += e2; s3 += e3;
        __nv_bfloat162 p0 = __floats2bfloat162_rn(e0, e1);
        __nv_bfloat162 p1 = __floats2bfloat162_rn(e2, e3);
        uint2 u;
        u.x = *(const uint32_t*)&p0;
        u.y = *(const uint32_t*)&p1;
        *(uint2*)&g_E[z][m0 + mrow][n0 + lane * 4] = u;
    }
    sacc[w][lane * 4 + 0] = s0;
    sacc[w][lane * 4 + 1] = s1;
    sacc[w][lane * 4 + 2] = s2;
    sacc[w][lane * 4 + 3] = s3;
    __syncthreads();
    if (t < 128) {
        float tot = sacc[0][t] + sacc[1][t] + sacc[2][t] + sacc[3][t]
                  + sacc[4][t] + sacc[5][t] + sacc[6][t] + sacc[7][t];
        atomicAdd(&g_S[z][n0 + t], tot);
    }
}

// ---------------- K3c: v'[c,n] = v[c,n]/S[n] -> bf16 -------------------------
__global__ void k_scaleVb() {
    int n4 = (blockIdx.x * 256 + threadIdx.x) * 4;
    int c = blockIdx.y;
    int z = blockIdx.z;
    float4 v = *(const float4*)&g_v[z][c][n4];
    float4 sv = *(const float4*)&g_S[z][n4];
    __nv_bfloat162 o[2];
    o[0] = __floats2bfloat162_rn(v.x / sv.x, v.y / sv.y);
    o[1] = __floats2bfloat162_rn(v.z / sv.z, v.w / sv.w);
    *(uint2*)&g_vb[z][c][n4] = *(const uint2*)o;
}

// ---------------- K4: bf16 mma.sync GEMM, 4 warps x (64c x 64m) tiles --------
#define KT 64
#define NKT (N_ / KT)
#define STG 3
#define STG_BYTES 32768
#define GEMM_SMEM (1024 + STG * STG_BYTES)

__global__ void __launch_bounds__(128, 2) k_gemm_mma(
        const float* __restrict__ fL, const float* __restrict__ fU,
        const float* __restrict__ beta_p, float* __restrict__ out) {
    extern __shared__ char dsm[];
    uint32_t sb0 = smem_u32(dsm);
    uint32_t sb = (sb0 + 1023) & ~1023u;

    int t = threadIdx.x, lane = t & 31, wid = t >> 5;
    int m0 = blockIdx.x * 128, c0 = blockIdx.y * 128, z = blockIdx.z;
    int dir = z >> 1, b = z & 1;
    int wc = wid >> 1, wm = wid & 1;                 // warp tile: 64c x 64m

    const __nv_bfloat16* Ab = &g_vb[z][c0][0];
    const __nv_bfloat16* Bb = &g_E[z][m0][0];

    int row  = t >> 3;            // 0..15
    int colb = (t & 7) * 16;

    float acc[4][8][4];
#pragma unroll
    for (int i = 0; i < 4; i++)
#pragma unroll
        for (int j = 0; j < 8; j++)
#pragma unroll
            for (int q = 0; q < 4; q++) acc[i][j][q] = 0.f;

    uint32_t aRow = (uint32_t)(wc * 64 + (lane & 15));
    uint32_t aKb  = (uint32_t)((lane >> 4) * 16);
    uint32_t bRow = (uint32_t)(wm * 64 + ((lane >> 4) & 1) * 8 + (lane & 7));
    uint32_t bKb  = (uint32_t)(((lane >> 3) & 1) * 16);

    // prologue: issue stages 0 and 1 (128 threads: 8 rows-passes each for A and B)
#pragma unroll
    for (int pk = 0; pk < 2; pk++) {
        uint32_t base = sb + pk * STG_BYTES;
        size_t kOff = (size_t)pk * KT * 2;
        const char* ap = (const char*)Ab + kOff + colb;
        const char* bp = (const char*)Bb + kOff + colb;
#pragma unroll
        for (int i = 0; i < 8; i++) {
            int r = row + i * 16;
            CPA(base + SWZ(r * 128 + colb), ap + (size_t)r * N_ * 2);
            CPA(base + 16384 + SWZ(r * 128 + colb), bp + (size_t)r * N_ * 2);
        }
        CPC();
    }

    int buf = 0;
    for (int kt = 0; kt < NKT; kt++) {
        CPW(1);
        __syncthreads();

        if (kt + 2 < NKT) {
            int nbuf = buf + 2; if (nbuf >= STG) nbuf -= STG;
            uint32_t base = sb + nbuf * STG_BYTES;
            size_t kOff = (size_t)(kt + 2) * KT * 2;
            const char* ap = (const char*)Ab + kOff + colb;
            const char* bp = (const char*)Bb + kOff + colb;
#pragma unroll
            for (int i = 0; i < 8; i++) {
                int r = row + i * 16;
                CPA(base + SWZ(r * 128 + colb), ap + (size_t)r * N_ * 2);
                CPA(base + 16384 + SWZ(r * 128 + colb), bp + (size_t)r * N_ * 2);
            }
            CPC();
        }

        uint32_t As = sb + buf * STG_BYTES;
        uint32_t Bs = As + 16384;
#pragma unroll
        for (int kk = 0; kk < 4; kk++) {
            uint32_t a[4][4], brg[4][4];
#pragma unroll
            for (int i = 0; i < 4; i++)
                ldsm4(a[i], As + SWZ((aRow + i * 16) * 128 + kk * 32 + aKb));
#pragma unroll
            for (int jj = 0; jj < 4; jj++)
                ldsm4(brg[jj], Bs + SWZ((bRow + jj * 16) * 128 + kk * 32 + bKb));
#pragma unroll
            for (int i = 0; i < 4; i++)
#pragma unroll
                for (int j = 0; j < 8; j++)
                    mma16816(acc[i][j], a[i], brg[j >> 1][(j & 1) * 2], brg[j >> 1][(j & 1) * 2 + 1]);
        }
        buf++; if (buf >= STG) buf -= STG;
    }

    float beta = *beta_p;
    const float* fsrc = dir ? fU : fL;
    float* osrc = out + (size_t)dir * B_ * C_ * N_;
#pragma unroll
    for (int i = 0; i < 4; i++) {
        int cr = c0 + wc * 64 + i * 16 + (lane >> 2);
#pragma unroll
        for (int j = 0; j < 8; j++) {
            int mc = m0 + wm * 64 + j * 8 + (lane & 3) * 2;
            size_t i0 = ((size_t)b * C_ + cr) * N_ + mc;
            size_t i1 = i0 + 8 * (size_t)N_;
            float2 f0 = *(const float2*)&fsrc[i0];
            float2 f1 = *(const float2*)&fsrc[i1];
            float2 d0, d1;
            d0.x = f0.x + beta * acc[i][j][0];
            d0.y = f0.y + beta * acc[i][j][1];
            d1.x = f1.x + beta * acc[i][j][2];
            d1.y = f1.y + beta * acc[i][j][3];
            *(float2*)&osrc[i0] = d0;
            *(float2*)&osrc[i1] = d1;
        }
    }
}

// ---------------- launch -----------------------------------------------------
extern "C" void kernel_launch(void* const* d_in, const int* in_sizes, int n_in,
                              void* d_out, int out_size) {
    const float* fL  = (const float*)d_in[0];
    const float* fU  = (const float*)d_in[1];
    const float* qLw = (const float*)d_in[2];
    const float* qLb = (const float*)d_in[3];
    const float* kUw = (const float*)d_in[4];
    const float* kUb = (const float*)d_in[5];
    const float* vUw = (const float*)d_in[6];
    const float* vUb = (const float*)d_in[7];
    const float* qUw = (const float*)d_in[8];
    const float* qUb = (const float*)d_in[9];
    const float* kLw = (const float*)d_in[10];
    const float* kLb = (const float*)d_in[11];
    const float* vLw = (const float*)d_in[12];
    const float* vLb = (const float*)d_in[13];
    const float* beta = (const float*)d_in[14];
    float* out = (float*)d_out;

    k_qkproj<<<dim3(N_ / 64, B_), 256>>>(fL, fU, qLw, qLb, kUw, kUb, qUw, qUb, kLw, kLb);
    k_vconv<<<dim3(N_ / 128, G_, DB), 128>>>(fL, fU, vUw, vUb, vLw, vLb);
    k_expT<<<dim3(N_ / 64, N_ / 128, DB), 256>>>();
    k_scaleVb<<<dim3(N_ / 1024, C_, DB), 256>>>();
    cudaFuncSetAttribute(k_gemm_mma, cudaFuncAttributeMaxDynamicSharedMemorySize, GEMM_SMEM);
    k_gemm_mma<<<dim3(N_ / 128, C_ / 128, DB), 128, GEMM_SMEM>>>(fL, fU, beta, out);
}

// round 16
// speedup vs baseline: 1.0375x; 1.0375x over previous
#include <cuda_runtime.h>
#include <cuda_bf16.h>
#include <cstdint>

#define B_   2
#define C_   256
#define N_   4096
#define R_   8
#define G_   4
#define CG_  64
#define DB   4        // DIRS*B_

// ---------------- scratch ---------------------------------------------------
__device__ float g_q[DB][R_][N_];
__device__ float g_k[DB][R_][N_];
__device__ float g_S[DB][N_];
__device__ __nv_bfloat16 g_vb[DB][C_][N_];          // v' in bf16 (A operand)
__device__ __nv_bfloat16 g_E[DB][N_][N_];           // Et[m][n] = exp(q_n . k_m)

// ---------------- helpers ----------------------------------------------------
__device__ __forceinline__ uint32_t smem_u32(const void* p) {
    uint32_t a;
    asm("{ .reg .u64 t; cvta.to.shared.u64 t, %1; cvt.u32.u64 %0, t; }" : "=r"(a) : "l"(p));
    return a;
}
#define SWZ(o) ((o) ^ (((o) >> 3) & 0x70))
#define CPA(s, g) asm volatile("cp.async.cg.shared.global [%0], [%1], 16;" :: "r"(s), "l"(g) : "memory")
#define CPC()     asm volatile("cp.async.commit_group;" ::: "memory")
#define CPW(n)    asm volatile("cp.async.wait_group %0;" :: "n"(n) : "memory")

__device__ __forceinline__ void ldsm4(uint32_t* r, uint32_t addr) {
    asm volatile("ldmatrix.sync.aligned.m8n8.x4.shared.b16 {%0,%1,%2,%3}, [%4];"
                 : "=r"(r[0]), "=r"(r[1]), "=r"(r[2]), "=r"(r[3]) : "r"(addr));
}
__device__ __forceinline__ void mma16816(float* d, const uint32_t* a, uint32_t b0, uint32_t b1) {
    asm volatile("mma.sync.aligned.m16n8k16.row.col.f32.bf16.bf16.f32 "
                 "{%0,%1,%2,%3}, {%4,%5,%6,%7}, {%8,%9}, {%0,%1,%2,%3};"
                 : "+f"(d[0]), "+f"(d[1]), "+f"(d[2]), "+f"(d[3])
                 : "r"(a[0]), "r"(a[1]), "r"(a[2]), "r"(a[3]), "r"(b0), "r"(b1));
}

// ---------------- K1: fused low-rank projections (+ S zeroing folded in) -----
__global__ void k_qkproj(const float* __restrict__ fL, const float* __restrict__ fU,
                         const float* __restrict__ qLw, const float* __restrict__ qLb,
                         const float* __restrict__ kUw, const float* __restrict__ kUb,
                         const float* __restrict__ qUw, const float* __restrict__ qUb,
                         const float* __restrict__ kLw, const float* __restrict__ kLb) {
    __shared__ float sbuf[8448];
    int t = threadIdx.x;
    int n0 = blockIdx.x * 64;
    int b  = blockIdx.y;
    int nl = t & 63, slice = t >> 6;

    if (t < 64) {
        g_S[b][n0 + t] = 0.f;
        g_S[2 + b][n0 + t] = 0.f;
    }

    for (int i = t; i < R_ * C_; i += 256) {
        sbuf[i] = qLw[i]; sbuf[2048 + i] = kUw[i]; sbuf[4096 + i] = qUw[i]; sbuf[6144 + i] = kLw[i];
    }
    __syncthreads();

    float aQL[R_], aKU[R_], aQU[R_], aKL[R_];
#pragma unroll
    for (int r = 0; r < R_; r++) { aQL[r]=0.f; aKU[r]=0.f; aQU[r]=0.f; aKL[r]=0.f; }
    const float* xl = fL + (size_t)b * C_ * N_ + n0 + nl;
    const float* xu = fU + (size_t)b * C_ * N_ + n0 + nl;
    for (int ci = 0; ci < 64; ci++) {
        int c = slice * 64 + ci;
        float vl = xl[(size_t)c * N_];
        float vu = xu[(size_t)c * N_];
#pragma unroll
        for (int r = 0; r < R_; r++) {
            aQL[r] = fmaf(sbuf[r * 256 + c], vl, aQL[r]);
            aKU[r] = fmaf(sbuf[2048 + r * 256 + c], vu, aKU[r]);
            aQU[r] = fmaf(sbuf[4096 + r * 256 + c], vu, aQU[r]);
            aKL[r] = fmaf(sbuf[6144 + r * 256 + c], vl, aKL[r]);
        }
    }
    __syncthreads();
    {
        float* red = &sbuf[(size_t)(slice * 64 + nl) * 33];
#pragma unroll
        for (int r = 0; r < R_; r++) {
            red[r] = aQL[r]; red[8 + r] = aKU[r]; red[16 + r] = aQU[r]; red[24 + r] = aKL[r];
        }
    }
    __syncthreads();
    {
        int n2 = t & 63, grp = t >> 6;
#pragma unroll
        for (int j = 0; j < R_; j++) {
            int o = grp * 8 + j;
            float s = sbuf[(0 * 64 + n2) * 33 + o] + sbuf[(1 * 64 + n2) * 33 + o]
                    + sbuf[(2 * 64 + n2) * 33 + o] + sbuf[(3 * 64 + n2) * 33 + o];
            int n = n0 + n2;
            if (grp == 0)      g_q[b][j][n]     = s + qLb[j];
            else if (grp == 1) g_k[b][j][n]     = s + kUb[j];
            else if (grp == 2) g_q[2 + b][j][n] = s + qUb[j];
            else               g_k[2 + b][j][n] = s + kLb[j];
        }
    }
}

// ---------------- K3: Et[m][n]=exp(q_n.k_m) bf16, coalesced, low-reg ---------
__global__ void __launch_bounds__(256) k_expT() {
    __shared__ float ks[64][9];
    __shared__ float sacc[8][128];
    int t = threadIdx.x, lane = t & 31, w = t >> 5;
    int m0 = blockIdx.x * 64;
    int n0 = blockIdx.y * 128;
    int z  = blockIdx.z;

    for (int i = t; i < 64 * R_; i += 256)
        ks[i >> 3][i & 7] = g_k[z][i & 7][m0 + (i >> 3)];

    float4 qr[R_];
#pragma unroll
    for (int r = 0; r < R_; r++)
        qr[r] = *(const float4*)&g_q[z][r][n0 + lane * 4];
    __syncthreads();

    float s0 = 0.f, s1 = 0.f, s2 = 0.f, s3 = 0.f;
#pragma unroll
    for (int mi = 0; mi < 8; mi++) {
        int mrow = w * 8 + mi;
        float l0 = 0.f, l1 = 0.f, l2 = 0.f, l3 = 0.f;
#pragma unroll
        for (int r = 0; r < R_; r++) {
            float km = ks[mrow][r];
            l0 = fmaf(qr[r].x, km, l0);
            l1 = fmaf(qr[r].y, km, l1);
            l2 = fmaf(qr[r].z, km, l2);
            l3 = fmaf(qr[r].w, km, l3);
        }
        float e0 = __expf(l0), e1 = __expf(l1), e2 = __expf(l2), e3 = __expf(l3);
        s0 += e0; s1 += e1; s2 += e2; s3 += e3;
        __nv_bfloat162 p0 = __floats2bfloat162_rn(e0, e1);
        __nv_bfloat162 p1 = __floats2bfloat162_rn(e2, e3);
        uint2 u;
        u.x = *(const uint32_t*)&p0;
        u.y = *(const uint32_t*)&p1;
        *(uint2*)&g_E[z][m0 + mrow][n0 + lane * 4] = u;
    }
    sacc[w][lane * 4 + 0] = s0;
    sacc[w][lane * 4 + 1] = s1;
    sacc[w][lane * 4 + 2] = s2;
    sacc[w][lane * 4 + 3] = s3;
    __syncthreads();
    if (t < 128) {
        float tot = sacc[0][t] + sacc[1][t] + sacc[2][t] + sacc[3][t]
                  + sacc[4][t] + sacc[5][t] + sacc[6][t] + sacc[7][t];
        atomicAdd(&g_S[z][n0 + t], tot);
    }
}

// ---------------- K2': grouped conv fused with 1/S scaling -> bf16 -----------
// replaces k_vconv + k_scaleVb; runs AFTER k_expT (needs final S).
__global__ void k_vscale(const float* __restrict__ fL, const float* __restrict__ fU,
                         const float* __restrict__ vUw, const float* __restrict__ vUb,
                         const float* __restrict__ vLw, const float* __restrict__ vLb) {
    __shared__ float xs[CG_][128];
    __shared__ float ws[CG_][CG_];
    int t  = threadIdx.x;            // 128
    int n0 = blockIdx.x * 128;
    int g  = blockIdx.y;
    int z  = blockIdx.z;
    int dir = z >> 1, b = z & 1;
    const float* x    = dir ? fL  : fU;
    const float* w    = dir ? vLw : vUw;
    const float* bias = dir ? vLb : vUb;
    for (int ci = 0; ci < CG_; ci++)
        xs[ci][t] = x[((size_t)b * C_ + g * CG_ + ci) * N_ + n0 + t];
    for (int i = t; i < CG_ * CG_; i += 128)
        (&ws[0][0])[i] = w[g * CG_ * CG_ + i];
    float rInv = 1.0f / g_S[z][n0 + t];
    __syncthreads();
    for (int co = 0; co < CG_; co++) {
        float acc = bias[g * CG_ + co];
#pragma unroll 8
        for (int ci = 0; ci < CG_; ci++)
            acc = fmaf(ws[co][ci], xs[ci][t], acc);
        g_vb[z][g * CG_ + co][n0 + t] = __float2bfloat16(acc * rInv);
    }
}

// ---------------- K4: bf16 mma.sync GEMM (R13 best: 8 warps 64x32, 3-stage) --
#define KT 64
#define NKT (N_ / KT)
#define STG 3
#define STG_BYTES 32768
#define GEMM_SMEM (1024 + STG * STG_BYTES)

__global__ void __launch_bounds__(256, 2) k_gemm_mma(
        const float* __restrict__ fL, const float* __restrict__ fU,
        const float* __restrict__ beta_p, float* __restrict__ out) {
    extern __shared__ char dsm[];
    uint32_t sb0 = smem_u32(dsm);
    uint32_t sb = (sb0 + 1023) & ~1023u;

    int t = threadIdx.x, lane = t & 31, wid = t >> 5;
    int m0 = blockIdx.x * 128, c0 = blockIdx.y * 128, z = blockIdx.z;
    int dir = z >> 1, b = z & 1;
    int wc = wid >> 2, wm = wid & 3;                 // warp tile: 64c x 32m

    const __nv_bfloat16* Ab = &g_vb[z][c0][0];
    const __nv_bfloat16* Bb = &g_E[z][m0][0];

    int row  = t >> 3;
    int colb = (t & 7) * 16;

    float acc[4][4][4];
#pragma unroll
    for (int i = 0; i < 4; i++)
#pragma unroll
        for (int j = 0; j < 4; j++)
#pragma unroll
            for (int q = 0; q < 4; q++) acc[i][j][q] = 0.f;

    uint32_t aRow = (uint32_t)(wc * 64 + (lane & 15));
    uint32_t aKb  = (uint32_t)((lane >> 4) * 16);
    uint32_t bRow = (uint32_t)(wm * 32 + ((lane >> 4) & 1) * 8 + (lane & 7));
    uint32_t bKb  = (uint32_t)(((lane >> 3) & 1) * 16);

    // prologue: issue stages 0 and 1
#pragma unroll
    for (int pk = 0; pk < 2; pk++) {
        uint32_t base = sb + pk * STG_BYTES;
        size_t kOff = (size_t)pk * KT * 2;
        const char* ap = (const char*)Ab + kOff + colb;
        const char* bp = (const char*)Bb + kOff + colb;
#pragma unroll
        for (int i = 0; i < 4; i++) {
            int r = row + i * 32;
            CPA(base + SWZ(r * 128 + colb), ap + (size_t)r * N_ * 2);
            CPA(base + 16384 + SWZ(r * 128 + colb), bp + (size_t)r * N_ * 2);
        }
        CPC();
    }

    int buf = 0;
    for (int kt = 0; kt < NKT; kt++) {
        CPW(1);                       // stage kt resident (only kt+1 may pend)
        __syncthreads();              // also fences prior iteration's reads

        if (kt + 2 < NKT) {           // issue stage kt+2 into the just-freed buffer
            int nbuf = buf + 2; if (nbuf >= STG) nbuf -= STG;
            uint32_t base = sb + nbuf * STG_BYTES;
            size_t kOff = (size_t)(kt + 2) * KT * 2;
            const char* ap = (const char*)Ab + kOff + colb;
            const char* bp = (const char*)Bb + kOff + colb;
#pragma unroll
            for (int i = 0; i < 4; i++) {
                int r = row + i * 32;
                CPA(base + SWZ(r * 128 + colb), ap + (size_t)r * N_ * 2);
                CPA(base + 16384 + SWZ(r * 128 + colb), bp + (size_t)r * N_ * 2);
            }
            CPC();
        }

        uint32_t As = sb + buf * STG_BYTES;
        uint32_t Bs = As + 16384;
#pragma unroll
        for (int kk = 0; kk < 4; kk++) {
            uint32_t a[4][4], brg[2][4];
#pragma unroll
            for (int i = 0; i < 4; i++)
                ldsm4(a[i], As + SWZ((aRow + i * 16) * 128 + kk * 32 + aKb));
#pragma unroll
            for (int jj = 0; jj < 2; jj++)
                ldsm4(brg[jj], Bs + SWZ((bRow + jj * 16) * 128 + kk * 32 + bKb));
#pragma unroll
            for (int i = 0; i < 4; i++)
#pragma unroll
                for (int j = 0; j < 4; j++)
                    mma16816(acc[i][j], a[i], brg[j >> 1][(j & 1) * 2], brg[j >> 1][(j & 1) * 2 + 1]);
        }
        buf++; if (buf >= STG) buf -= STG;
    }

    float beta = *beta_p;
    const float* fsrc = dir ? fU : fL;
    float* osrc = out + (size_t)dir * B_ * C_ * N_;
#pragma unroll
    for (int i = 0; i < 4; i++) {
        int cr = c0 + wc * 64 + i * 16 + (lane >> 2);
#pragma unroll
        for (int j = 0; j < 4; j++) {
            int mc = m0 + wm * 32 + j * 8 + (lane & 3) * 2;
            size_t i0 = ((size_t)b * C_ + cr) * N_ + mc;
            size_t i1 = i0 + 8 * (size_t)N_;
            float2 f0 = *(const float2*)&fsrc[i0];
            float2 f1 = *(const float2*)&fsrc[i1];
            float2 d0, d1;
            d0.x = f0.x + beta * acc[i][j][0];
            d0.y = f0.y + beta * acc[i][j][1];
            d1.x = f1.x + beta * acc[i][j][2];
            d1.y = f1.y + beta * acc[i][j][3];
            *(float2*)&osrc[i0] = d0;
            *(float2*)&osrc[i1] = d1;
        }
    }
}

// ---------------- launch -----------------------------------------------------
extern "C" void kernel_launch(void* const* d_in, const int* in_sizes, int n_in,
                              void* d_out, int out_size) {
    const float* fL  = (const float*)d_in[0];
    const float* fU  = (const float*)d_in[1];
    const float* qLw = (const float*)d_in[2];
    const float* qLb = (const float*)d_in[3];
    const float* kUw = (const float*)d_in[4];
    const float* kUb = (const float*)d_in[5];
    const float* vUw = (const float*)d_in[6];
    const float* vUb = (const float*)d_in[7];
    const float* qUw = (const float*)d_in[8];
    const float* qUb = (const float*)d_in[9];
    const float* kLw = (const float*)d_in[10];
    const float* kLb = (const float*)d_in[11];
    const float* vLw = (const float*)d_in[12];
    const float* vLb = (const float*)d_in[13];
    const float* beta = (const float*)d_in[14];
    float* out = (float*)d_out;

    k_qkproj<<<dim3(N_ / 64, B_), 256>>>(fL, fU, qLw, qLb, kUw, kUb, qUw, qUb, kLw, kLb);
    k_expT<<<dim3(N_ / 64, N_ / 128, DB), 256>>>();
    k_vscale<<<dim3(N_ / 128, G_, DB), 128>>>(fL, fU, vUw, vUb, vLw, vLb);
    cudaFuncSetAttribute(k_gemm_mma, cudaFuncAttributeMaxDynamicSharedMemorySize, GEMM_SMEM);
    k_gemm_mma<<<dim3(N_ / 128, C_ / 128, DB), 256, GEMM_SMEM>>>(fL, fU, beta, out);
}